// round 8
// baseline (speedup 1.0000x reference)
#include <cuda_runtime.h>
#include <cstdint>

#define S_LEN 2048
#define B_SZ  256
#define H_SZ  256
#define NI    128
#define NO    128

typedef unsigned long long ull;

// Scratch (allocation-free)
__device__ float g_Zx[(size_t)S_LEN * B_SZ * H_SZ];   // (t, b, h)
__device__ float g_H [(size_t)S_LEN * B_SZ * H_SZ];   // (t, b, k)
__device__ float g_sum[S_LEN][H_SZ];                  // per-step BN sum (RED)
__device__ float g_sq [S_LEN][H_SZ];                  // per-step BN sumsq (RED)
__device__ unsigned g_cnt[32];                        // padded step counter

__device__ __forceinline__ float gelu_f(float x) {
    return 0.5f * x * (1.0f + erff(x * 0.70710678118654752440f));
}

// ---- packed f32x2 helpers (sm_103a) ----
__device__ __forceinline__ void fma2(ull& d, ull a, ull b) {
    asm("fma.rn.f32x2 %0, %1, %2, %3;" : "=l"(d) : "l"(a), "l"(b), "l"(d));
}
__device__ __forceinline__ ull add2(ull a, ull b) {
    ull r; asm("add.rn.f32x2 %0, %1, %2;" : "=l"(r) : "l"(a), "l"(b)); return r;
}
__device__ __forceinline__ ull pack2(float x, float y) {
    ull r; asm("mov.b64 %0, {%1, %2};" : "=l"(r) : "f"(x), "f"(y)); return r;
}
__device__ __forceinline__ float2 unpack2(ull v) {
    float2 f; asm("mov.b64 {%0, %1}, %2;" : "=f"(f.x), "=f"(f.y) : "l"(v)); return f;
}

// ---- cluster / sync helpers ----
__device__ __forceinline__ unsigned ctarank() {
    unsigned r; asm("mov.u32 %0, %%cluster_ctarank;" : "=r"(r)); return r;
}
__device__ __forceinline__ unsigned smem_u32(const void* p) {
    return (unsigned)__cvta_generic_to_shared(p);
}
__device__ __forceinline__ unsigned mapa_peer(unsigned laddr, unsigned rank) {
    unsigned r;
    asm("mapa.shared::cluster.u32 %0, %1, %2;" : "=r"(r) : "r"(laddr), "r"(rank));
    return r;
}
__device__ __forceinline__ void st_cluster_f2(unsigned addr, float x, float y) {
    asm volatile("st.shared::cluster.v2.f32 [%0], {%1, %2};"
                 :: "r"(addr), "f"(x), "f"(y) : "memory");
}
__device__ __forceinline__ void cluster_sync_() {
    asm volatile("barrier.cluster.arrive.aligned;" ::: "memory");
    asm volatile("barrier.cluster.wait.aligned;" ::: "memory");
}
__device__ __forceinline__ void red_addf(float* p, float v) {
    asm volatile("red.global.add.f32 [%0], %1;" :: "l"(p), "f"(v) : "memory");
}
__device__ __forceinline__ unsigned ld_acq(const unsigned* p) {
    unsigned v;
    asm volatile("ld.global.acquire.gpu.u32 %0, [%1];" : "=r"(v) : "l"(p));
    return v;
}

__global__ void init_kernel() {
    const size_t n = (size_t)S_LEN * H_SZ;
    const size_t stride = (size_t)gridDim.x * blockDim.x;
    for (size_t i = (size_t)blockIdx.x * blockDim.x + threadIdx.x; i < n; i += stride) {
        ((float*)g_sum)[i] = 0.f;
        ((float*)g_sq)[i]  = 0.f;
    }
    if (blockIdx.x == 0 && threadIdx.x < 32) g_cnt[threadIdx.x] = 0u;
}

// ---------------------------------------------------------------------------
// Kernel A: Zx[t,b,n] = sum_i X[b,t,i] * W_ih[n,i] + b_ih[n]
// ---------------------------------------------------------------------------
__global__ void __launch_bounds__(256) proj_in_kernel(
    const float* __restrict__ X, const float* __restrict__ W_ih,
    const float* __restrict__ b_ih)
{
    __shared__ float As[16][132];
    __shared__ float Bs[16][68];
    const int tid = threadIdx.x;
    const int r0  = blockIdx.x * 128;
    const int n0  = blockIdx.y * 64;
    const int t   = r0 >> 8;
    const int b0  = r0 & 255;
    const int tx  = tid & 15, ty = tid >> 4;

    float acc[8][4];
    #pragma unroll
    for (int i = 0; i < 8; ++i)
        #pragma unroll
        for (int j = 0; j < 4; ++j) acc[i][j] = 0.f;

    const int kq = (tid & 3) * 4;
    const int am = tid >> 2;

    for (int k0 = 0; k0 < NI; k0 += 16) {
        #pragma unroll
        for (int h = 0; h < 2; ++h) {
            const int m = am + h * 64;
            const float4 v = *(const float4*)(X + (size_t)(b0 + m) * (S_LEN * NI)
                                              + (size_t)t * NI + k0 + kq);
            As[kq + 0][m] = v.x; As[kq + 1][m] = v.y;
            As[kq + 2][m] = v.z; As[kq + 3][m] = v.w;
        }
        {
            const float4 v = *(const float4*)(W_ih + (size_t)(n0 + am) * 384 + k0 + kq);
            Bs[kq + 0][am] = v.x; Bs[kq + 1][am] = v.y;
            Bs[kq + 2][am] = v.z; Bs[kq + 3][am] = v.w;
        }
        __syncthreads();
        #pragma unroll
        for (int kk = 0; kk < 16; ++kk) {
            const float4 a0 = *(const float4*)&As[kk][ty * 8];
            const float4 a1 = *(const float4*)&As[kk][ty * 8 + 4];
            const float4 bv = *(const float4*)&Bs[kk][tx * 4];
            const float a[8] = {a0.x, a0.y, a0.z, a0.w, a1.x, a1.y, a1.z, a1.w};
            const float bb[4] = {bv.x, bv.y, bv.z, bv.w};
            #pragma unroll
            for (int i = 0; i < 8; ++i)
                #pragma unroll
                for (int j = 0; j < 4; ++j) acc[i][j] = fmaf(a[i], bb[j], acc[i][j]);
        }
        __syncthreads();
    }
    const float4 bv = *(const float4*)(b_ih + n0 + tx * 4);
    #pragma unroll
    for (int i = 0; i < 8; ++i) {
        float4 o;
        o.x = acc[i][0] + bv.x; o.y = acc[i][1] + bv.y;
        o.z = acc[i][2] + bv.z; o.w = acc[i][3] + bv.w;
        *(float4*)(g_Zx + (size_t)(r0 + ty * 8 + i) * 256 + n0 + tx * 4) = o;
    }
}

// ---------------------------------------------------------------------------
// Kernel B: clustered recurrence, COLUMN-split clusters (R7 protocol), with
// the per-thread remote mbarrier arrivals replaced by ONE cluster.sync.
// 64 clusters x 2 CTAs; cluster owns 4 batch rows; CTA owns a 128-col half
// end-to-end; k split into 4 register quarters (wreg 64 ull/thread).
// Per step: reg matvec -> one intra-CTA smem reduce -> z complete ->
// RED stats (own cols) -> S2 -> tid0 fence+atomic -> acquire-poll -> S3 ->
// stats -> gelu (2 erf/thread) -> h2 local + DSMEM push -> cluster.sync.
// ---------------------------------------------------------------------------
__global__ void __launch_bounds__(256, 1) __cluster_dims__(2, 1, 1)
rec_kernel(const float* __restrict__ W_ih, const float* __restrict__ gamma,
           const float* __restrict__ beta)
{
    __shared__ float  h2[256][8];        // full-k h, 4 rows duplicated pairs (8 KB)
    __shared__ float2 redb[4][4][64];    // [kq][row][cpl] (8 KB)

    const int tid  = threadIdx.x;
    const unsigned rank = ctarank();
    const int b0   = (blockIdx.x >> 1) * 4;
    const int kq   = tid >> 6;           // matvec: k-quarter; finalize: row
    const int cpl  = tid & 63;           // local col pair
    const int gc   = (int)rank * 128 + cpl * 2;

    // W quarter in registers: wreg[i] = {W[gk][gc], W[gk][gc+1]}, gk = kq*64+i
    ull wreg[64];
    {
        const float* w0p = W_ih + (size_t)gc * 384 + NI + kq * 64;
        const float* w1p = W_ih + (size_t)(gc + 1) * 384 + NI + kq * 64;
        #pragma unroll
        for (int i = 0; i < 64; ++i) wreg[i] = pack2(w0p[i], w1p[i]);
    }
    const float gam0 = gamma[gc], gam1 = gamma[gc + 1];
    const float bet0 = beta[gc],  bet1 = beta[gc + 1];

    const unsigned* cnt = &g_cnt[0];

    for (int t = 0; t < S_LEN; ++t) {
        // prefetch Zx for finalize slot (row = kq)
        const float2 zx = __ldcg((const float2*)(g_Zx
                            + ((size_t)t * 256 + b0 + kq) * 256 + gc));

        ull a0 = 0ull, a1 = 0ull, a2 = 0ull, a3 = 0ull;
        if (t > 0) {
            const int kb = kq * 64;
            #pragma unroll
            for (int i = 0; i < 64; ++i) {
                const ulonglong2 p01 = *(const ulonglong2*)&h2[kb + i][0];
                const ulonglong2 p23 = *(const ulonglong2*)&h2[kb + i][4];
                fma2(a0, p01.x, wreg[i]);
                fma2(a1, p01.y, wreg[i]);
                fma2(a2, p23.x, wreg[i]);
                fma2(a3, p23.y, wreg[i]);
            }
        }
        redb[kq][0][cpl] = unpack2(a0);
        redb[kq][1][cpl] = unpack2(a1);
        redb[kq][2][cpl] = unpack2(a2);
        redb[kq][3][cpl] = unpack2(a3);
        __syncthreads();                               // S1

        // finalize: row r = kq, cols gc, gc+1  (z complete inside the CTA)
        const float2 q0 = redb[0][kq][cpl];
        const float2 q1 = redb[1][kq][cpl];
        const float2 q2 = redb[2][kq][cpl];
        const float2 q3 = redb[3][kq][cpl];
        ull z2 = add2(add2(pack2(q0.x, q0.y), pack2(q1.x, q1.y)),
                      add2(pack2(q2.x, q2.y), pack2(q3.x, q3.y)));
        z2 = add2(z2, pack2(zx.x, zx.y));
        const float2 zf = unpack2(z2);

        red_addf(&g_sum[t][gc],     zf.x);
        red_addf(&g_sum[t][gc + 1], zf.y);
        red_addf(&g_sq [t][gc],     zf.x * zf.x);
        red_addf(&g_sq [t][gc + 1], zf.y * zf.y);
        __syncthreads();                               // S2
        if (tid == 0) {
            __threadfence();                           // order REDs before signal
            atomicAdd(&g_cnt[0], 1u);
            const unsigned tgt = 128u * (unsigned)(t + 1);
            while (ld_acq(cnt) < tgt) { }
        }
        __syncthreads();                               // S3

        const float2 sm = __ldcg((const float2*)&g_sum[t][gc]);
        const float2 sq = __ldcg((const float2*)&g_sq[t][gc]);
        const float mu0 = sm.x * (1.f / 256.f);
        const float mu1 = sm.y * (1.f / 256.f);
        const float v0  = fmaf(-mu0, mu0, sq.x * (1.f / 256.f));
        const float v1  = fmaf(-mu1, mu1, sq.y * (1.f / 256.f));
        const float k0  = rsqrtf(v0 + 1e-5f) * gam0;
        const float k1  = rsqrtf(v1 + 1e-5f) * gam1;
        const float h0 = gelu_f(fmaf(zf.x - mu0, k0, bet0));
        const float h1 = gelu_f(fmaf(zf.y - mu1, k1, bet1));

        // local h2 (dup pairs) + remote push + g_H (own cols, row = kq)
        const int r = kq;
        *(float2*)&h2[gc][2 * r]     = make_float2(h0, h0);
        *(float2*)&h2[gc + 1][2 * r] = make_float2(h1, h1);
        st_cluster_f2(mapa_peer(smem_u32(&h2[gc][2 * r]),     rank ^ 1u), h0, h0);
        st_cluster_f2(mapa_peer(smem_u32(&h2[gc + 1][2 * r]), rank ^ 1u), h1, h1);
        *(float2*)(g_H + ((size_t)t * 256 + b0 + r) * 256 + gc) = make_float2(h0, h1);

        // one HW cluster barrier: publishes DSMEM pushes (arrive=release,
        // wait=acquire) and doubles as the end-of-step CTA barrier.
        cluster_sync_();
    }
}

// ---------------------------------------------------------------------------
// Kernel C: out[b,t,n] = gelu( sum_k H[t,b,k] * W_ho[n,k] + b_ho[n] )
// ---------------------------------------------------------------------------
__global__ void __launch_bounds__(256) proj_out_kernel(
    const float* __restrict__ W_ho, const float* __restrict__ b_ho,
    float* __restrict__ out)
{
    __shared__ float As[16][132];
    __shared__ float Bs[16][68];
    const int tid = threadIdx.x;
    const int r0  = blockIdx.x * 128;
    const int n0  = blockIdx.y * 64;
    const int t   = r0 >> 8;
    const int b0  = r0 & 255;
    const int tx  = tid & 15, ty = tid >> 4;

    float acc[8][4];
    #pragma unroll
    for (int i = 0; i < 8; ++i)
        #pragma unroll
        for (int j = 0; j < 4; ++j) acc[i][j] = 0.f;

    const int kq = (tid & 3) * 4;
    const int am = tid >> 2;

    for (int k0 = 0; k0 < H_SZ; k0 += 16) {
        #pragma unroll
        for (int h = 0; h < 2; ++h) {
            const int m = am + h * 64;
            const float4 v = *(const float4*)(g_H + (size_t)(r0 + m) * 256 + k0 + kq);
            As[kq + 0][m] = v.x; As[kq + 1][m] = v.y;
            As[kq + 2][m] = v.z; As[kq + 3][m] = v.w;
        }
        {
            const float4 v = *(const float4*)(W_ho + (size_t)(n0 + am) * H_SZ + k0 + kq);
            Bs[kq + 0][am] = v.x; Bs[kq + 1][am] = v.y;
            Bs[kq + 2][am] = v.z; Bs[kq + 3][am] = v.w;
        }
        __syncthreads();
        #pragma unroll
        for (int kk = 0; kk < 16; ++kk) {
            const float4 a0 = *(const float4*)&As[kk][ty * 8];
            const float4 a1 = *(const float4*)&As[kk][ty * 8 + 4];
            const float4 bv = *(const float4*)&Bs[kk][tx * 4];
            const float a[8] = {a0.x, a0.y, a0.z, a0.w, a1.x, a1.y, a1.z, a1.w};
            const float bb[4] = {bv.x, bv.y, bv.z, bv.w};
            #pragma unroll
            for (int i = 0; i < 8; ++i)
                #pragma unroll
                for (int j = 0; j < 4; ++j) acc[i][j] = fmaf(a[i], bb[j], acc[i][j]);
        }
        __syncthreads();
    }
    const float4 bv = *(const float4*)(b_ho + n0 + tx * 4);
    #pragma unroll
    for (int i = 0; i < 8; ++i) {
        float4 o;
        o.x = gelu_f(acc[i][0] + bv.x);
        o.y = gelu_f(acc[i][1] + bv.y);
        o.z = gelu_f(acc[i][2] + bv.z);
        o.w = gelu_f(acc[i][3] + bv.w);
        *(float4*)(out + (size_t)(b0 + ty * 8 + i) * (S_LEN * NO)
                   + (size_t)t * NO + n0 + tx * 4) = o;
    }
}

// ---------------------------------------------------------------------------
extern "C" void kernel_launch(void* const* d_in, const int* in_sizes, int n_in,
                              void* d_out, int out_size)
{
    const float* X     = (const float*)d_in[0];
    const float* W_ih  = (const float*)d_in[1];
    const float* b_ih  = (const float*)d_in[2];
    const float* W_ho  = (const float*)d_in[3];
    const float* b_ho  = (const float*)d_in[4];
    const float* gamma = (const float*)d_in[5];
    const float* beta  = (const float*)d_in[6];
    float* out = (float*)d_out;

    init_kernel<<<256, 256>>>();
    proj_in_kernel<<<dim3((S_LEN * B_SZ) / 128, H_SZ / 64), 256>>>(X, W_ih, b_ih);
    rec_kernel<<<128, 256>>>(W_ih, gamma, beta);
    proj_out_kernel<<<dim3((S_LEN * B_SZ) / 128, NO / 64), 256>>>(W_ho, b_ho, out);
}

// round 9
// speedup vs baseline: 2.4584x; 2.4584x over previous
#include <cuda_runtime.h>
#include <cstdint>

#define S_LEN 2048
#define B_SZ  256
#define H_SZ  256
#define NI    128
#define NO    128

typedef unsigned long long ull;

// Scratch (allocation-free)
__device__ float g_Zx[(size_t)S_LEN * B_SZ * H_SZ];   // (t, b, h)
__device__ float g_H [(size_t)S_LEN * B_SZ * H_SZ];   // (t, b, k)
__device__ float g_sum[S_LEN][H_SZ];                  // per-step BN sum (RED)
__device__ float g_sq [S_LEN][H_SZ];                  // per-step BN sumsq (RED)
__device__ unsigned g_cnt[32];                        // padded step counter

__device__ __forceinline__ float gelu_f(float x) {
    return 0.5f * x * (1.0f + erff(x * 0.70710678118654752440f));
}

// ---- packed f32x2 helpers (sm_103a) ----
__device__ __forceinline__ void fma2(ull& d, ull a, ull b) {
    asm("fma.rn.f32x2 %0, %1, %2, %3;" : "=l"(d) : "l"(a), "l"(b), "l"(d));
}
__device__ __forceinline__ ull add2(ull a, ull b) {
    ull r; asm("add.rn.f32x2 %0, %1, %2;" : "=l"(r) : "l"(a), "l"(b)); return r;
}
__device__ __forceinline__ ull pack2(float x, float y) {
    ull r; asm("mov.b64 %0, {%1, %2};" : "=l"(r) : "f"(x), "f"(y)); return r;
}
__device__ __forceinline__ float2 unpack2(ull v) {
    float2 f; asm("mov.b64 {%0, %1}, %2;" : "=f"(f.x), "=f"(f.y) : "l"(v)); return f;
}

// ---- cluster / sync helpers ----
__device__ __forceinline__ unsigned ctarank() {
    unsigned r; asm("mov.u32 %0, %%cluster_ctarank;" : "=r"(r)); return r;
}
__device__ __forceinline__ unsigned smem_u32(const void* p) {
    return (unsigned)__cvta_generic_to_shared(p);
}
__device__ __forceinline__ unsigned mapa_peer(unsigned laddr, unsigned rank) {
    unsigned r;
    asm("mapa.shared::cluster.u32 %0, %1, %2;" : "=r"(r) : "r"(laddr), "r"(rank));
    return r;
}
__device__ __forceinline__ void st_cluster_f2(unsigned addr, float x, float y) {
    asm volatile("st.shared::cluster.v2.f32 [%0], {%1, %2};"
                 :: "r"(addr), "f"(x), "f"(y) : "memory");
}
__device__ __forceinline__ void cluster_sync_() {
    asm volatile("barrier.cluster.arrive.aligned;" ::: "memory");
    asm volatile("barrier.cluster.wait.aligned;" ::: "memory");
}
__device__ __forceinline__ void red_addf(float* p, float v) {
    asm volatile("red.global.add.f32 [%0], %1;" :: "l"(p), "f"(v) : "memory");
}

__global__ void init_kernel() {
    const size_t n = (size_t)S_LEN * H_SZ;
    const size_t stride = (size_t)gridDim.x * blockDim.x;
    for (size_t i = (size_t)blockIdx.x * blockDim.x + threadIdx.x; i < n; i += stride) {
        ((float*)g_sum)[i] = 0.f;
        ((float*)g_sq)[i]  = 0.f;
    }
    if (blockIdx.x == 0 && threadIdx.x < 32) g_cnt[threadIdx.x] = 0u;
}

// ---------------------------------------------------------------------------
// Kernel A: Zx[t,b,n] = sum_i X[b,t,i] * W_ih[n,i] + b_ih[n]
// ---------------------------------------------------------------------------
__global__ void __launch_bounds__(256) proj_in_kernel(
    const float* __restrict__ X, const float* __restrict__ W_ih,
    const float* __restrict__ b_ih)
{
    __shared__ float As[16][132];
    __shared__ float Bs[16][68];
    const int tid = threadIdx.x;
    const int r0  = blockIdx.x * 128;
    const int n0  = blockIdx.y * 64;
    const int t   = r0 >> 8;
    const int b0  = r0 & 255;
    const int tx  = tid & 15, ty = tid >> 4;

    float acc[8][4];
    #pragma unroll
    for (int i = 0; i < 8; ++i)
        #pragma unroll
        for (int j = 0; j < 4; ++j) acc[i][j] = 0.f;

    const int kq = (tid & 3) * 4;
    const int am = tid >> 2;

    for (int k0 = 0; k0 < NI; k0 += 16) {
        #pragma unroll
        for (int h = 0; h < 2; ++h) {
            const int m = am + h * 64;
            const float4 v = *(const float4*)(X + (size_t)(b0 + m) * (S_LEN * NI)
                                              + (size_t)t * NI + k0 + kq);
            As[kq + 0][m] = v.x; As[kq + 1][m] = v.y;
            As[kq + 2][m] = v.z; As[kq + 3][m] = v.w;
        }
        {
            const float4 v = *(const float4*)(W_ih + (size_t)(n0 + am) * 384 + k0 + kq);
            Bs[kq + 0][am] = v.x; Bs[kq + 1][am] = v.y;
            Bs[kq + 2][am] = v.z; Bs[kq + 3][am] = v.w;
        }
        __syncthreads();
        #pragma unroll
        for (int kk = 0; kk < 16; ++kk) {
            const float4 a0 = *(const float4*)&As[kk][ty * 8];
            const float4 a1 = *(const float4*)&As[kk][ty * 8 + 4];
            const float4 bv = *(const float4*)&Bs[kk][tx * 4];
            const float a[8] = {a0.x, a0.y, a0.z, a0.w, a1.x, a1.y, a1.z, a1.w};
            const float bb[4] = {bv.x, bv.y, bv.z, bv.w};
            #pragma unroll
            for (int i = 0; i < 8; ++i)
                #pragma unroll
                for (int j = 0; j < 4; ++j) acc[i][j] = fmaf(a[i], bb[j], acc[i][j]);
        }
        __syncthreads();
    }
    const float4 bv = *(const float4*)(b_ih + n0 + tx * 4);
    #pragma unroll
    for (int i = 0; i < 8; ++i) {
        float4 o;
        o.x = acc[i][0] + bv.x; o.y = acc[i][1] + bv.y;
        o.z = acc[i][2] + bv.z; o.w = acc[i][3] + bv.w;
        *(float4*)(g_Zx + (size_t)(r0 + ty * 8 + i) * 256 + n0 + tx * 4) = o;
    }
}

// ---------------------------------------------------------------------------
// Kernel B: R6 k-split clustered recurrence, finalize split over 256 threads.
// 64 clusters x 2 CTAs; cluster owns 4 batch rows; CTA rank owns k-half
// [rank*128, rank*128+128) of W_h in registers (64 ull/thread, 2 cols).
// Per step: reg matvec (kq = 64-k quarter) -> redb[kq] -> S1 ->
// kq0 combines + pushes CTA-total z-partial to peer zbuf -> cluster.sync ->
// finalize (ALL 256 threads, 1 col x 4 rows, 4 erf) -> rank0 REDs (1/addr
// per cluster) -> fence -> 64-arrival counter -> stats -> h2 local -> S4.
// ---------------------------------------------------------------------------
__global__ void __launch_bounds__(256, 1) __cluster_dims__(2, 1, 1)
rec_kernel(const float* __restrict__ W_ih, const float* __restrict__ gamma,
           const float* __restrict__ beta)
{
    __shared__ float  h2[128][8];        // own k-half h, 4 rows dup pairs (4 KB)
    __shared__ float2 redb[2][4][128];   // own partials [kq][row][cp] (8 KB)
    __shared__ float2 zbuf[2][4][128];   // peer totals, parity (8 KB)

    const int tid  = threadIdx.x;
    const unsigned rank = ctarank();
    const int b0   = (blockIdx.x >> 1) * 4;
    const int kq   = tid >> 7;           // 0..1: 64-k quarter of own k-half
    const int cp   = tid & 127;          // col pair (matvec role)
    const int c2   = cp * 2;

    // W quarter in registers: wreg[i] = {W[gk][c2], W[gk][c2+1]},
    // gk = rank*128 + kq*64 + i
    ull wreg[64];
    {
        const int kbase = NI + (int)rank * 128 + kq * 64;
        const float* w0p = W_ih + (size_t)c2 * 384 + kbase;
        const float* w1p = W_ih + (size_t)(c2 + 1) * 384 + kbase;
        #pragma unroll
        for (int i = 0; i < 64; ++i) wreg[i] = pack2(w0p[i], w1p[i]);
    }
    // finalize role: this thread owns column c = tid (4 batch rows)
    const float gam = gamma[tid];
    const float bet = beta[tid];

    volatile unsigned* vcnt = (volatile unsigned*)&g_cnt[0];

    for (int t = 0; t < S_LEN; ++t) {
        // prefetch Zx for finalize column: 4 rows, scalar coalesced
        float zx0 = __ldcg(g_Zx + ((size_t)t * 256 + b0 + 0) * 256 + tid);
        float zx1 = __ldcg(g_Zx + ((size_t)t * 256 + b0 + 1) * 256 + tid);
        float zx2 = __ldcg(g_Zx + ((size_t)t * 256 + b0 + 2) * 256 + tid);
        float zx3 = __ldcg(g_Zx + ((size_t)t * 256 + b0 + 3) * 256 + tid);

        ull a0 = 0ull, a1 = 0ull, a2 = 0ull, a3 = 0ull;
        if (t > 0) {
            const int kb = kq * 64;
            #pragma unroll
            for (int i = 0; i < 64; ++i) {
                const ulonglong2 p01 = *(const ulonglong2*)&h2[kb + i][0];
                const ulonglong2 p23 = *(const ulonglong2*)&h2[kb + i][4];
                fma2(a0, p01.x, wreg[i]);
                fma2(a1, p01.y, wreg[i]);
                fma2(a2, p23.x, wreg[i]);
                fma2(a3, p23.y, wreg[i]);
            }
        }
        redb[kq][0][cp] = unpack2(a0);
        redb[kq][1][cp] = unpack2(a1);
        redb[kq][2][cp] = unpack2(a2);
        redb[kq][3][cp] = unpack2(a3);
        __syncthreads();                               // S1

        const int par = t & 1;
        if (kq == 0) {
            // CTA total for this col pair = own acc + kq1 partial; push to peer
            #pragma unroll
            for (int r = 0; r < 4; ++r) {
                const float2 o = redb[1][r][cp];
                ull tot = (r == 0 ? a0 : r == 1 ? a1 : r == 2 ? a2 : a3);
                tot = add2(tot, pack2(o.x, o.y));
                const float2 v = unpack2(tot);
                st_cluster_f2(mapa_peer(smem_u32(&zbuf[par][r][cp]), rank ^ 1u),
                              v.x, v.y);
            }
        }
        cluster_sync_();   // publishes zbuf pushes both directions

        // ---- finalize: column c = tid, 4 rows ----
        const int cpx = tid >> 1;
        const int comp = tid & 1;
        float z0, z1, z2, z3;
        {
            #pragma unroll
            for (int r = 0; r < 4; ++r) {
                const float2 ra = redb[0][r][cpx];
                const float2 rb = redb[1][r][cpx];
                const float2 zp = zbuf[par][r][cpx];
                const float own = comp ? (ra.y + rb.y) : (ra.x + rb.x);
                const float peer = comp ? zp.y : zp.x;
                const float zz = own + peer +
                    (r == 0 ? zx0 : r == 1 ? zx1 : r == 2 ? zx2 : zx3);
                if (r == 0) z0 = zz; else if (r == 1) z1 = zz;
                else if (r == 2) z2 = zz; else z3 = zz;
            }
        }
        if (rank == 0) {
            const float s = (z0 + z1) + (z2 + z3);
            const float q = (z0 * z0 + z1 * z1) + (z2 * z2 + z3 * z3);
            red_addf(&g_sum[t][tid], s);
            red_addf(&g_sq [t][tid], q);
        }
        __threadfence();                               // drain REDs to L2
        __syncthreads();                               // S2
        if (tid == 0) {
            if (rank == 0) atomicAdd(&g_cnt[0], 1u);
            const unsigned tgt = 64u * (unsigned)(t + 1);
            while (*vcnt < tgt) { }
            __threadfence();
        }
        __syncthreads();                               // S3

        const float sm = __ldcg(&g_sum[t][tid]);
        const float sq = __ldcg(&g_sq[t][tid]);
        const float mu  = sm * (1.f / 256.f);
        const float var = fmaf(-mu, mu, sq * (1.f / 256.f));
        const float ks  = rsqrtf(var + 1e-5f) * gam;
        const float h0 = gelu_f(fmaf(z0 - mu, ks, bet));
        const float h1 = gelu_f(fmaf(z1 - mu, ks, bet));
        const float h3v = gelu_f(fmaf(z3 - mu, ks, bet));
        const float h2v = gelu_f(fmaf(z2 - mu, ks, bet));

        // local h2 store if col in own k-half
        if ((tid >> 7) == (int)rank) {
            const int kl = tid & 127;
            *(float4*)&h2[kl][0] = make_float4(h0, h0, h1, h1);
            *(float4*)&h2[kl][4] = make_float4(h2v, h2v, h3v, h3v);
        }
        // g_H (t,b,k) for proj_out; rank0 only, scalar coalesced
        if (rank == 0) {
            g_H[((size_t)t * 256 + b0 + 0) * 256 + tid] = h0;
            g_H[((size_t)t * 256 + b0 + 1) * 256 + tid] = h1;
            g_H[((size_t)t * 256 + b0 + 2) * 256 + tid] = h2v;
            g_H[((size_t)t * 256 + b0 + 3) * 256 + tid] = h3v;
        }
        __syncthreads();                               // S4: h2 ready
    }
}

// ---------------------------------------------------------------------------
// Kernel C: out[b,t,n] = gelu( sum_k H[t,b,k] * W_ho[n,k] + b_ho[n] )
// ---------------------------------------------------------------------------
__global__ void __launch_bounds__(256) proj_out_kernel(
    const float* __restrict__ W_ho, const float* __restrict__ b_ho,
    float* __restrict__ out)
{
    __shared__ float As[16][132];
    __shared__ float Bs[16][68];
    const int tid = threadIdx.x;
    const int r0  = blockIdx.x * 128;
    const int n0  = blockIdx.y * 64;
    const int t   = r0 >> 8;
    const int b0  = r0 & 255;
    const int tx  = tid & 15, ty = tid >> 4;

    float acc[8][4];
    #pragma unroll
    for (int i = 0; i < 8; ++i)
        #pragma unroll
        for (int j = 0; j < 4; ++j) acc[i][j] = 0.f;

    const int kq = (tid & 3) * 4;
    const int am = tid >> 2;

    for (int k0 = 0; k0 < H_SZ; k0 += 16) {
        #pragma unroll
        for (int h = 0; h < 2; ++h) {
            const int m = am + h * 64;
            const float4 v = *(const float4*)(g_H + (size_t)(r0 + m) * 256 + k0 + kq);
            As[kq + 0][m] = v.x; As[kq + 1][m] = v.y;
            As[kq + 2][m] = v.z; As[kq + 3][m] = v.w;
        }
        {
            const float4 v = *(const float4*)(W_ho + (size_t)(n0 + am) * H_SZ + k0 + kq);
            Bs[kq + 0][am] = v.x; Bs[kq + 1][am] = v.y;
            Bs[kq + 2][am] = v.z; Bs[kq + 3][am] = v.w;
        }
        __syncthreads();
        #pragma unroll
        for (int kk = 0; kk < 16; ++kk) {
            const float4 a0 = *(const float4*)&As[kk][ty * 8];
            const float4 a1 = *(const float4*)&As[kk][ty * 8 + 4];
            const float4 bv = *(const float4*)&Bs[kk][tx * 4];
            const float a[8] = {a0.x, a0.y, a0.z, a0.w, a1.x, a1.y, a1.z, a1.w};
            const float bb[4] = {bv.x, bv.y, bv.z, bv.w};
            #pragma unroll
            for (int i = 0; i < 8; ++i)
                #pragma unroll
                for (int j = 0; j < 4; ++j) acc[i][j] = fmaf(a[i], bb[j], acc[i][j]);
        }
        __syncthreads();
    }
    const float4 bv = *(const float4*)(b_ho + n0 + tx * 4);
    #pragma unroll
    for (int i = 0; i < 8; ++i) {
        float4 o;
        o.x = gelu_f(acc[i][0] + bv.x);
        o.y = gelu_f(acc[i][1] + bv.y);
        o.z = gelu_f(acc[i][2] + bv.z);
        o.w = gelu_f(acc[i][3] + bv.w);
        *(float4*)(out + (size_t)(b0 + ty * 8 + i) * (S_LEN * NO)
                   + (size_t)t * NO + n0 + tx * 4) = o;
    }
}

// ---------------------------------------------------------------------------
extern "C" void kernel_launch(void* const* d_in, const int* in_sizes, int n_in,
                              void* d_out, int out_size)
{
    const float* X     = (const float*)d_in[0];
    const float* W_ih  = (const float*)d_in[1];
    const float* b_ih  = (const float*)d_in[2];
    const float* W_ho  = (const float*)d_in[3];
    const float* b_ho  = (const float*)d_in[4];
    const float* gamma = (const float*)d_in[5];
    const float* beta  = (const float*)d_in[6];
    float* out = (float*)d_out;

    init_kernel<<<256, 256>>>();
    proj_in_kernel<<<dim3((S_LEN * B_SZ) / 128, H_SZ / 64), 256>>>(X, W_ih, b_ih);
    rec_kernel<<<128, 256>>>(W_ih, gamma, beta);
    proj_out_kernel<<<dim3((S_LEN * B_SZ) / 128, NO / 64), 256>>>(W_ho, b_ho, out);
}